// round 1
// baseline (speedup 1.0000x reference)
#include <cuda_runtime.h>
#include <cuda_bf16.h>
#include <cstdint>

// Elementwise: out = tanh((x0*x1 + sin(x2))*exp(-|x3|) + x4/(x5^2+exp(x6)) - x7)
// Layout: row-major [N_ROWS, 8] fp32 -> each row is exactly two float4.
// 4 rows per thread: 8x LDG.128 front-batched (MLP), 1x STG.128 out.

__global__ __launch_bounds__(256) void expr_kernel(
    const float4* __restrict__ in,   // N_ROWS*2 float4
    float4* __restrict__ out,        // N_ROWS/4 float4
    int n_quads)                     // N_ROWS/4
{
    int t = blockIdx.x * blockDim.x + threadIdx.x;
    if (t >= n_quads) return;

    const float4* p = in + (size_t)t * 8;

    // Front-batch all 8 loads for max memory-level parallelism.
    float4 a0 = p[0], b0 = p[1];
    float4 a1 = p[2], b1 = p[3];
    float4 a2 = p[4], b2 = p[5];
    float4 a3 = p[6], b3 = p[7];

    float4 res;

    {
        float e = (a0.x * a0.y + __sinf(a0.z)) * __expf(-fabsf(a0.w))
                + __fdividef(b0.x, b0.y * b0.y + __expf(b0.z)) - b0.w;
        res.x = tanhf(e);
    }
    {
        float e = (a1.x * a1.y + __sinf(a1.z)) * __expf(-fabsf(a1.w))
                + __fdividef(b1.x, b1.y * b1.y + __expf(b1.z)) - b1.w;
        res.y = tanhf(e);
    }
    {
        float e = (a2.x * a2.y + __sinf(a2.z)) * __expf(-fabsf(a2.w))
                + __fdividef(b2.x, b2.y * b2.y + __expf(b2.z)) - b2.w;
        res.z = tanhf(e);
    }
    {
        float e = (a3.x * a3.y + __sinf(a3.z)) * __expf(-fabsf(a3.w))
                + __fdividef(b3.x, b3.y * b3.y + __expf(b3.z)) - b3.w;
        res.w = tanhf(e);
    }

    out[t] = res;
}

extern "C" void kernel_launch(void* const* d_in, const int* in_sizes, int n_in,
                              void* d_out, int out_size)
{
    const float4* in = (const float4*)d_in[0];
    float4* out = (float4*)d_out;

    int n_rows = out_size;           // one output per row
    int n_quads = n_rows / 4;        // 8388608 / 4 = 2097152

    int threads = 256;
    int blocks = (n_quads + threads - 1) / threads;
    expr_kernel<<<blocks, threads>>>(in, out, n_quads);
}

// round 2
// speedup vs baseline: 1.3450x; 1.3450x over previous
#include <cuda_runtime.h>
#include <cuda_bf16.h>
#include <cstdint>

// out[r] = tanh((x0*x1 + sin(x2))*exp(-|x3|) + x4/(x5^2+exp(x6)) - x7)
// One row per thread: two LDG.128 at 32B lane stride (2x L1 wavefront
// inflation, vs 8x in the 4-rows/thread version), STG.32 fully coalesced.

__global__ __launch_bounds__(256) void expr_kernel(
    const float4* __restrict__ in,   // N_ROWS*2 float4
    float* __restrict__ out,         // N_ROWS floats
    int n_rows)
{
    int t = blockIdx.x * blockDim.x + threadIdx.x;
    if (t >= n_rows) return;

    // Front-batch both loads (independent, same two cache lines per 4-lane group).
    float4 a = in[2 * t];      // x0 x1 x2 x3
    float4 b = in[2 * t + 1];  // x4 x5 x6 x7

    float e = (a.x * a.y + __sinf(a.z)) * __expf(-fabsf(a.w))
            + __fdividef(b.x, b.y * b.y + __expf(b.z)) - b.w;

    out[t] = tanhf(e);
}

extern "C" void kernel_launch(void* const* d_in, const int* in_sizes, int n_in,
                              void* d_out, int out_size)
{
    const float4* in = (const float4*)d_in[0];
    float* out = (float*)d_out;

    int n_rows = out_size;   // 8388608
    int threads = 256;
    int blocks = (n_rows + threads - 1) / threads;
    expr_kernel<<<blocks, threads>>>(in, out, n_rows);
}

// round 3
// speedup vs baseline: 1.3615x; 1.0123x over previous
#include <cuda_runtime.h>
#include <cuda_bf16.h>
#include <cstdint>

// out[r] = tanh((x0*x1 + sin(x2))*exp(-|x3|) + x4/(x5^2+exp(x6)) - x7)
// 2 rows/thread (warp-contiguous mapping keeps 32B-lane-stride coalescing),
// 4 front-batched LDG.128.CS for MLP, streaming hints since zero reuse.

__global__ __launch_bounds__(256) void expr_kernel(
    const float4* __restrict__ in,   // N_ROWS*2 float4
    float* __restrict__ out,         // N_ROWS floats
    int n_rows)
{
    const int tid = threadIdx.x;
    int r0 = blockIdx.x * 512 + tid;        // rows [base, base+256)
    int r1 = r0 + 256;                      // rows [base+256, base+512)

    if (r1 < n_rows) {
        // Front-batch all 4 loads for MLP=4.
        float4 a0 = __ldcs(in + 2 * r0);
        float4 b0 = __ldcs(in + 2 * r0 + 1);
        float4 a1 = __ldcs(in + 2 * r1);
        float4 b1 = __ldcs(in + 2 * r1 + 1);

        float e0 = (a0.x * a0.y + __sinf(a0.z)) * __expf(-fabsf(a0.w))
                 + __fdividef(b0.x, b0.y * b0.y + __expf(b0.z)) - b0.w;
        float e1 = (a1.x * a1.y + __sinf(a1.z)) * __expf(-fabsf(a1.w))
                 + __fdividef(b1.x, b1.y * b1.y + __expf(b1.z)) - b1.w;

        __stcs(out + r0, tanhf(e0));
        __stcs(out + r1, tanhf(e1));
    } else if (r0 < n_rows) {
        float4 a = __ldcs(in + 2 * r0);
        float4 b = __ldcs(in + 2 * r0 + 1);
        float e = (a.x * a.y + __sinf(a.z)) * __expf(-fabsf(a.w))
                + __fdividef(b.x, b.y * b.y + __expf(b.z)) - b.w;
        __stcs(out + r0, tanhf(e));
    }
}

extern "C" void kernel_launch(void* const* d_in, const int* in_sizes, int n_in,
                              void* d_out, int out_size)
{
    const float4* in = (const float4*)d_in[0];
    float* out = (float*)d_out;

    int n_rows = out_size;   // 8388608
    int threads = 256;
    int rows_per_block = threads * 2;
    int blocks = (n_rows + rows_per_block - 1) / rows_per_block;  // 16384
    expr_kernel<<<blocks, threads>>>(in, out, n_rows);
}

// round 4
// speedup vs baseline: 1.4055x; 1.0323x over previous
#include <cuda_runtime.h>
#include <cuda_bf16.h>
#include <cstdint>

// out[r] = tanh((x0*x1 + sin(x2))*exp(-|x3|) + x4/(x5^2+exp(x6)) - x7)
// 4 rows/thread, warp-contiguous mapping (row = base + tid + k*256) keeps the
// 32B-lane-stride coalescing; 8 front-batched LDG.128.CS -> MLP=8/thread.

__global__ __launch_bounds__(256) void expr_kernel(
    const float4* __restrict__ in,   // N_ROWS*2 float4
    float* __restrict__ out,         // N_ROWS floats
    int n_rows)
{
    const int tid = threadIdx.x;
    const int base = blockIdx.x * 1024 + tid;   // 1024 rows per block

    const int r0 = base;
    const int r1 = base + 256;
    const int r2 = base + 512;
    const int r3 = base + 768;

    if (r3 < n_rows) {
        // Front-batch all 8 loads for maximum memory-level parallelism.
        float4 a0 = __ldcs(in + 2 * r0);
        float4 b0 = __ldcs(in + 2 * r0 + 1);
        float4 a1 = __ldcs(in + 2 * r1);
        float4 b1 = __ldcs(in + 2 * r1 + 1);
        float4 a2 = __ldcs(in + 2 * r2);
        float4 b2 = __ldcs(in + 2 * r2 + 1);
        float4 a3 = __ldcs(in + 2 * r3);
        float4 b3 = __ldcs(in + 2 * r3 + 1);

        float e0 = (a0.x * a0.y + __sinf(a0.z)) * __expf(-fabsf(a0.w))
                 + __fdividef(b0.x, b0.y * b0.y + __expf(b0.z)) - b0.w;
        float e1 = (a1.x * a1.y + __sinf(a1.z)) * __expf(-fabsf(a1.w))
                 + __fdividef(b1.x, b1.y * b1.y + __expf(b1.z)) - b1.w;
        float e2 = (a2.x * a2.y + __sinf(a2.z)) * __expf(-fabsf(a2.w))
                 + __fdividef(b2.x, b2.y * b2.y + __expf(b2.z)) - b2.w;
        float e3 = (a3.x * a3.y + __sinf(a3.z)) * __expf(-fabsf(a3.w))
                 + __fdividef(b3.x, b3.y * b3.y + __expf(b3.z)) - b3.w;

        __stcs(out + r0, tanhf(e0));
        __stcs(out + r1, tanhf(e1));
        __stcs(out + r2, tanhf(e2));
        __stcs(out + r3, tanhf(e3));
    } else {
        #pragma unroll
        for (int k = 0; k < 4; k++) {
            int r = base + k * 256;
            if (r < n_rows) {
                float4 a = __ldcs(in + 2 * r);
                float4 b = __ldcs(in + 2 * r + 1);
                float e = (a.x * a.y + __sinf(a.z)) * __expf(-fabsf(a.w))
                        + __fdividef(b.x, b.y * b.y + __expf(b.z)) - b.w;
                __stcs(out + r, tanhf(e));
            }
        }
    }
}

extern "C" void kernel_launch(void* const* d_in, const int* in_sizes, int n_in,
                              void* d_out, int out_size)
{
    const float4* in = (const float4*)d_in[0];
    float* out = (float*)d_out;

    int n_rows = out_size;   // 8388608
    int threads = 256;
    int rows_per_block = threads * 4;
    int blocks = (n_rows + rows_per_block - 1) / rows_per_block;  // 8192
    expr_kernel<<<blocks, threads>>>(in, out, n_rows);
}